// round 4
// baseline (speedup 1.0000x reference)
#include <cuda_runtime.h>
#include <cuda_bf16.h>

// FocalLoss: inputs [B, A] f32 probs, targets [A, B] i32 {0,1}, attr_loss_weight [A] f32.
// loss = sum_b mean_a( aw[a] * (1-x)^2 * bce(x, t) ),  bce = -log(t ? clamp(x) : 1-clamp(x))
// B = 1e6, A = 40. Memory-bound streaming reduction (320 MB read).

#define A_NUM 40
#define NTHREADS 256
#define NBLOCKS  1184   // 148 SMs * 8

__global__ void fl_init_out(float* out) {
    if (threadIdx.x == 0) out[0] = 0.0f;
}

__device__ __forceinline__ float fl_elem(float x, int t, float w) {
    // lower clip only: upper bound 1-1e-12 rounds to 1.0f in f32 (matches f32 reference)
    float p = fmaxf(x, 1e-12f);
    float q = t ? p : (1.0f - p);
    float d = 1.0f - x;
    // w already includes attr weight * (1/A)
    return w * d * d * (-__logf(q));
}

__global__ __launch_bounds__(NTHREADS) void focal_loss_kernel(
    const float* __restrict__ in,     // [B, A]
    const int*   __restrict__ tg,     // [A, B]
    const float* __restrict__ aw,     // [A]
    float*       __restrict__ out,    // scalar
    int B, int A)
{
    extern __shared__ float aws[];
    for (int a = threadIdx.x; a < A; a += blockDim.x)
        aws[a] = aw[a] * (1.0f / (float)A);
    __syncthreads();

    const int stride = gridDim.x * blockDim.x;
    float acc = 0.0f;

    if (A == A_NUM) {
        // Fast path: A=40, divisible by 4, so a float4 of `in` never crosses a row.
        const float4* __restrict__ in4 = reinterpret_cast<const float4*>(in);
        const int NV = (B / 4) * A_NUM;          // == B*A/4 elements of float4

        for (int i = blockIdx.x * blockDim.x + threadIdx.x; i < NV; i += stride) {
            float4 x = in4[i];
            int e = i * 4;                       // element index
            int b = e / A_NUM;
            int a = e - b * A_NUM;               // a in {0,4,...,36}

            const int* tp = tg + a * B + b;
            int t0 = __ldg(tp);
            int t1 = __ldg(tp + B);
            int t2 = __ldg(tp + 2 * B);
            int t3 = __ldg(tp + 3 * B);

            acc += fl_elem(x.x, t0, aws[a]);
            acc += fl_elem(x.y, t1, aws[a + 1]);
            acc += fl_elem(x.z, t2, aws[a + 2]);
            acc += fl_elem(x.w, t3, aws[a + 3]);
        }
    } else {
        // Generic scalar fallback (never taken for the registered shape).
        long long N = (long long)B * A;
        for (long long e = blockIdx.x * blockDim.x + threadIdx.x; e < N; e += stride) {
            int b = (int)(e / A);
            int a = (int)(e - (long long)b * A);
            float x = in[e];
            int t = __ldg(tg + (long long)a * B + b);
            acc += fl_elem(x, t, aws[a]);
        }
    }

    // warp reduce
    #pragma unroll
    for (int o = 16; o > 0; o >>= 1)
        acc += __shfl_down_sync(0xFFFFFFFFu, acc, o);

    __shared__ float wsum[NTHREADS / 32];
    int lane = threadIdx.x & 31;
    int wid  = threadIdx.x >> 5;
    if (lane == 0) wsum[wid] = acc;
    __syncthreads();

    if (threadIdx.x < NTHREADS / 32) {
        float v = wsum[threadIdx.x];
        #pragma unroll
        for (int o = (NTHREADS / 32) / 2; o > 0; o >>= 1)
            v += __shfl_down_sync(0xFFu, v, o);
        if (threadIdx.x == 0)
            atomicAdd(out, v);
    }
}

extern "C" void kernel_launch(void* const* d_in, const int* in_sizes, int n_in,
                              void* d_out, int out_size) {
    const float* inputs  = (const float*)d_in[0];   // [B, A] f32
    const int*   targets = (const int*)d_in[1];     // [A, B] i32
    const float* aw      = (const float*)d_in[2];   // [A] f32
    float* out = (float*)d_out;

    int A = in_sizes[2];
    int B = in_sizes[0] / A;

    fl_init_out<<<1, 32>>>(out);
    size_t smem = (size_t)A * sizeof(float);
    focal_loss_kernel<<<NBLOCKS, NTHREADS, smem>>>(inputs, targets, aw, out, B, A);
}

// round 5
// speedup vs baseline: 1.0030x; 1.0030x over previous
#include <cuda_runtime.h>
#include <cuda_bf16.h>

// FocalLoss: inputs [B, A] f32 probs, targets [A, B] i32 {0,1}, attr_loss_weight [A] f32.
// loss = sum_b mean_a( aw[a] * (1-x)^2 * bce(x, t) ),  bce = -log(t ? clamp(x) : 1-clamp(x))
// B = 1e6, A = 40.  Memory-bound streaming reduction (320 MB read).
//
// R5: stage targets through smem per 80-sample chunk so ALL global loads are
// fully coalesced (int4 targets, float4 inputs). Fixes R4's L1tex bottleneck
// (L1=88%, DRAM=60%) caused by ~10-line-per-instruction scalar target loads.

#define A_NUM    40
#define NB       80          // samples per chunk (1e6 % 80 == 0)
#define BSTR     84          // smem byte stride per attr row (pad kills bank conflicts)
#define NTHREADS 256
#define NBLOCKS  1184        // 148 SMs * 8 blocks

#define LN2_F 0.6931471805599453f

__global__ void fl_init_out(float* out) {
    if (threadIdx.x == 0) out[0] = 0.0f;
}

// w includes aw[a] * ln2 / A ;  -log(q) = -log2(q) * ln2
__device__ __forceinline__ float fl_elem(float x, int t, float w) {
    float p   = fmaxf(x, 1e-12f);     // upper clip 1-1e-12 rounds to 1.0f in f32
    float omp = 1.0f - p;
    float q   = t ? p : omp;
    float d   = 1.0f - x;
    return w * (d * d) * (-__log2f(q));
}

__global__ __launch_bounds__(NTHREADS, 8) void focal_loss_kernel(
    const float* __restrict__ in,     // [B, A]
    const int*   __restrict__ tg,     // [A, B]
    const float* __restrict__ aw,     // [A]
    float*       __restrict__ out,    // scalar
    int B, int A)
{
    __shared__ float         awv[A_NUM];
    __shared__ unsigned char ts[A_NUM * BSTR];   // 3360 B target stage

    float acc = 0.0f;
    const int tid = threadIdx.x;

    if (A == A_NUM && (B % NB) == 0) {
        if (tid < A_NUM) awv[tid] = aw[tid] * (LN2_F / (float)A_NUM);
        // first __syncthreads below (after phase 1) also covers awv visibility

        const float4* __restrict__ in4 = reinterpret_cast<const float4*>(in);
        const int nchunks = B / NB;                 // 12500
        const int NI4     = NB * A_NUM / 4;         // 800 int4/float4 per chunk

        for (int c = blockIdx.x; c < nchunks; c += gridDim.x) {
            const int b0 = c * NB;

            // ---- Phase 1: targets -> smem (fully coalesced int4 loads) ----
            for (int j = tid; j < NI4; j += NTHREADS) {
                int a = j / (NB / 4);               // j / 20
                int r = j - a * (NB / 4);
                int4 tv = *reinterpret_cast<const int4*>(tg + a * B + b0 + 4 * r);
                uchar4 u = make_uchar4((unsigned char)tv.x, (unsigned char)tv.y,
                                       (unsigned char)tv.z, (unsigned char)tv.w);
                *reinterpret_cast<uchar4*>(ts + a * BSTR + 4 * r) = u;   // conflict-free
            }
            __syncthreads();

            // ---- Phase 2: stream inputs, read targets/weights from smem ----
            for (int i = tid; i < NI4; i += NTHREADS) {
                float4 x = in4[c * NI4 + i];
                int e  = 4 * i;
                int b  = e / A_NUM;                 // 0..79
                int a4 = e - A_NUM * b;             // 0,4,...,36

                const unsigned char* tp = ts + a4 * BSTR + b;
                int t0 = tp[0];
                int t1 = tp[BSTR];
                int t2 = tp[2 * BSTR];
                int t3 = tp[3 * BSTR];

                float4 w = *reinterpret_cast<const float4*>(awv + a4);

                acc += fl_elem(x.x, t0, w.x);
                acc += fl_elem(x.y, t1, w.y);
                acc += fl_elem(x.z, t2, w.z);
                acc += fl_elem(x.w, t3, w.w);
            }
            __syncthreads();                        // smem reuse guard
        }
    } else {
        // Generic fallback (not taken for the registered shape).
        long long N = (long long)B * A;
        const int stride = gridDim.x * blockDim.x;
        for (long long e = blockIdx.x * blockDim.x + tid; e < N; e += stride) {
            int b = (int)(e / A);
            int a = (int)(e - (long long)b * A);
            float x = in[e];
            int t = __ldg(tg + (long long)a * B + b);
            float w = __ldg(aw + a) * (LN2_F / (float)A);
            acc += fl_elem(x, t, w);
        }
    }

    // ---- block reduction + one atomic ----
    #pragma unroll
    for (int o = 16; o > 0; o >>= 1)
        acc += __shfl_down_sync(0xFFFFFFFFu, acc, o);

    __shared__ float wsum[NTHREADS / 32];
    int lane = tid & 31;
    int wid  = tid >> 5;
    if (lane == 0) wsum[wid] = acc;
    __syncthreads();

    if (tid < NTHREADS / 32) {
        float v = wsum[tid];
        #pragma unroll
        for (int o = (NTHREADS / 32) / 2; o > 0; o >>= 1)
            v += __shfl_down_sync(0xFFu, v, o);
        if (tid == 0)
            atomicAdd(out, v);
    }
}

extern "C" void kernel_launch(void* const* d_in, const int* in_sizes, int n_in,
                              void* d_out, int out_size) {
    const float* inputs  = (const float*)d_in[0];   // [B, A] f32
    const int*   targets = (const int*)d_in[1];     // [A, B] i32
    const float* aw      = (const float*)d_in[2];   // [A] f32
    float* out = (float*)d_out;

    int A = in_sizes[2];
    int B = in_sizes[0] / A;

    fl_init_out<<<1, 32>>>(out);
    focal_loss_kernel<<<NBLOCKS, NTHREADS>>>(inputs, targets, aw, out, B, A);
}

// round 8
// speedup vs baseline: 1.1187x; 1.1154x over previous
#include <cuda_runtime.h>
#include <cuda_bf16.h>

// FocalLoss: inputs [B, A] f32 probs, targets [A, B] i32 {0,1}, attr_loss_weight [A] f32.
// loss = sum_b mean_a( aw[a] * (1-x)^2 * bce(x, t) ),  bce = -log(t ? clamp(x) : 1-clamp(x))
// B = 1e6, A = 40.  ~324 MB streaming reduction.
//
// R6: double-buffered target staging (1 sync/chunk, next-chunk global loads overlap
// compute), all addressing hoisted (per-thread constants), weights in registers,
// 8 front-batched global loads per thread per chunk for high MLP.

#define A_NUM    40
#define NB       100               // samples per chunk (1e6 / 100 = 10000 chunks)
#define BSTR     104               // smem byte stride per attr row
#define NTHREADS 256
#define GRID     592               // 148 SMs * 4 CTAs; 10000/592 = 16.89 chunks/block
#define NI4      1000              // float4 (and int4) ops per chunk = NB*A/4

#define LN2_F 0.6931471805599453f

__global__ void fl_init_out(float* out) {
    if (threadIdx.x == 0) out[0] = 0.0f;
}

__device__ __forceinline__ float fl_elem(float x, int t, float w) {
    // p = max(x,1e-12); upper clip (1-1e-12) rounds to 1.0f in f32 -> no-op.
    // (1-x)^2 == (1-p)^2 exactly: for x >= 1e-12 p==x; for x < 1e-12 both round to 1.0f.
    float p   = fmaxf(x, 1e-12f);
    float omp = 1.0f - p;
    float q   = t ? p : omp;
    return -w * (omp * omp) * __log2f(q);   // w includes aw*ln2/A
}

__global__ __launch_bounds__(NTHREADS, 4) void focal_loss_kernel(
    const float* __restrict__ in,     // [B, A]
    const int*   __restrict__ tg,     // [A, B]
    const float* __restrict__ aw,     // [A]
    float*       __restrict__ out,    // scalar
    int B, int A)
{
    float acc = 0.0f;
    const int tid = threadIdx.x;

    if (A == A_NUM && (B % NB) == 0) {
        __shared__ __align__(16) float awv[A_NUM];
        __shared__ unsigned char ts[2][A_NUM * BSTR];   // 2 x 4160 B

        if (tid < A_NUM) awv[tid] = aw[tid] * (LN2_F / (float)A_NUM);

        const float4* __restrict__ in4 = reinterpret_cast<const float4*>(in);
        const int nchunks = B / NB;

        // ---- per-thread loop-invariant addressing ----
        // phase-2 (compute): i_k = tid + 256k  -> sample b_k, attrs a4_k..a4_k+3
        int  iK[4], bK[4], a4K[4], offK[4];
        bool vC[4];
        // phase-1 (target prefetch): j_k = tid + 256k -> attr taK, int4 index trK
        int  gK[4], sK[4];
        bool vT[4];
        #pragma unroll
        for (int k = 0; k < 4; k++) {
            int i = tid + NTHREADS * k;
            vC[k]  = (i < NI4);
            iK[k]  = i;
            bK[k]  = i / 10;                  // b = 4i/40
            a4K[k] = 4 * (i - 10 * bK[k]);    // a4 = 4*(i%10)
            offK[k] = a4K[k] * BSTR + bK[k];

            int j = tid + NTHREADS * k;
            vT[k] = (j < NI4);
            int ta = j / (NB / 4);            // j / 25
            int tr = j - ta * (NB / 4);
            gK[k] = ta * B + 4 * tr;          // + b0 at use
            sK[k] = ta * BSTR + 4 * tr;
        }

        // ---- prologue: prefetch targets of first chunk into buf 0 ----
        const int c0 = blockIdx.x;
        unsigned int P[4];
        #pragma unroll
        for (int k = 0; k < 4; k++) {
            P[k] = 0;
            if (vT[k]) {
                int4 tv = *reinterpret_cast<const int4*>(tg + gK[k] + c0 * NB);
                P[k] = (unsigned int)tv.x | ((unsigned int)tv.y << 8) |
                       ((unsigned int)tv.z << 16) | ((unsigned int)tv.w << 24);
            }
        }
        #pragma unroll
        for (int k = 0; k < 4; k++)
            if (vT[k]) *reinterpret_cast<unsigned int*>(&ts[0][sK[k]]) = P[k];
        __syncthreads();

        // per-thread weight quads (after awv visible)
        float4 w4[4];
        #pragma unroll
        for (int k = 0; k < 4; k++)
            w4[k] = *reinterpret_cast<const float4*>(awv + a4K[k]);

        int cur = 0;
        for (int c = c0; c < nchunks; c += GRID) {
            const int  cn = c + GRID;
            const bool pn = (cn < nchunks);

            // ---- issue next-chunk target loads (overlap with compute) ----
            #pragma unroll
            for (int k = 0; k < 4; k++) {
                if (pn && vT[k]) {
                    int4 tv = *reinterpret_cast<const int4*>(tg + gK[k] + cn * NB);
                    P[k] = (unsigned int)tv.x | ((unsigned int)tv.y << 8) |
                           ((unsigned int)tv.z << 16) | ((unsigned int)tv.w << 24);
                }
            }

            // ---- front-batched input loads ----
            float4 x[4];
            #pragma unroll
            for (int k = 0; k < 4; k++)
                if (vC[k]) x[k] = in4[c * NI4 + iK[k]];

            // ---- compute ----
            const unsigned char* tb = ts[cur];
            #pragma unroll
            for (int k = 0; k < 4; k++) {
                if (vC[k]) {
                    const unsigned char* tp = tb + offK[k];
                    int t0 = tp[0];
                    int t1 = tp[BSTR];
                    int t2 = tp[2 * BSTR];
                    int t3 = tp[3 * BSTR];
                    acc += fl_elem(x[k].x, t0, w4[k].x);
                    acc += fl_elem(x[k].y, t1, w4[k].y);
                    acc += fl_elem(x[k].z, t2, w4[k].z);
                    acc += fl_elem(x[k].w, t3, w4[k].w);
                }
            }

            // ---- store next-chunk targets into the other buffer ----
            if (pn) {
                #pragma unroll
                for (int k = 0; k < 4; k++)
                    if (vT[k]) *reinterpret_cast<unsigned int*>(&ts[cur ^ 1][sK[k]]) = P[k];
            }
            __syncthreads();
            cur ^= 1;
        }
    } else {
        // Generic fallback (not taken for the registered shape).
        long long N = (long long)B * A;
        const int stride = gridDim.x * blockDim.x;
        for (long long e = blockIdx.x * blockDim.x + tid; e < N; e += stride) {
            int b = (int)(e / A);
            int a = (int)(e - (long long)b * A);
            float x = in[e];
            int t = __ldg(tg + (long long)a * B + b);
            float w = __ldg(aw + a) * (LN2_F / (float)A);
            acc += fl_elem(x, t, w);
        }
    }

    // ---- block reduction + one atomic ----
    #pragma unroll
    for (int o = 16; o > 0; o >>= 1)
        acc += __shfl_down_sync(0xFFFFFFFFu, acc, o);

    __shared__ float wsum[NTHREADS / 32];
    int lane = tid & 31;
    int wid  = tid >> 5;
    if (lane == 0) wsum[wid] = acc;
    __syncthreads();

    if (tid < NTHREADS / 32) {
        float v = wsum[tid];
        #pragma unroll
        for (int o = (NTHREADS / 32) / 2; o > 0; o >>= 1)
            v += __shfl_down_sync(0xFFu, v, o);
        if (tid == 0)
            atomicAdd(out, v);
    }
}

extern "C" void kernel_launch(void* const* d_in, const int* in_sizes, int n_in,
                              void* d_out, int out_size) {
    const float* inputs  = (const float*)d_in[0];   // [B, A] f32
    const int*   targets = (const int*)d_in[1];     // [A, B] i32
    const float* aw      = (const float*)d_in[2];   // [A] f32
    float* out = (float*)d_out;

    int A = in_sizes[2];
    int B = in_sizes[0] / A;

    fl_init_out<<<1, 32>>>(out);
    focal_loss_kernel<<<GRID, NTHREADS>>>(inputs, targets, aw, out, B, A);
}